// round 16
// baseline (speedup 1.0000x reference)
#include <cuda_runtime.h>
#include <cuda_fp16.h>
#include <cuda_bf16.h>
#include <mma.h>
using namespace nvcuda;

#define NN 50000
#define NNP 50048  // padded to 128-row multiple (391*128)
#define NE 800000
#define HID 64
#define MAXD 128   // per-node bucket capacity (Poisson(16) tail @128 ~ 0)
#define NPW 4      // nodes per warp in gather kernels

// ---------------- scratch (device globals; no allocation allowed) -------------
__device__ float   g_xs[NN * 4];        // dinv[n] * x[n]
__device__ __half  g_h[NNP * HID];      // post-relu hidden state (fp16)
__device__ __half  g_m[NNP * HID];      // GEMM output, pre-scaled by dinv (fp16)
__device__ float   g_z[NN];             // pre-scaled final scalar
__device__ float   g_dinv[NNP];         // tail stays 0 (never written)
__device__ int     g_cnt[NN];
__device__ int     g_col[NN * MAXD];    // bucketed CSR (row n at n*MAXD)

// ---------------- CSR build (bucketed: count IS scatter) -----------------------
__global__ void k_scatter_count(const int* __restrict__ ei) {
    int e = blockIdx.x * blockDim.x + threadIdx.x;
    if (e < NE) {
        int s = ei[e];
        int d = ei[NE + e];
        int pos = atomicAdd(&g_cnt[d], 1);
        if (pos < MAXD) g_col[d * MAXD + pos] = s;
    }
}

__global__ void k_dinv_xs(const float* __restrict__ x) {
    int i = blockIdx.x * blockDim.x + threadIdx.x;
    if (i < NN) {
        float di = rsqrtf((float)(g_cnt[i] + 1));  // +1 self loop
        g_dinv[i] = di;
        float4 v = ((const float4*)x)[i];
        v.x *= di; v.y *= di; v.z *= di; v.w *= di;
        ((float4*)g_xs)[i] = v;
    }
}

// ---- per-node fp16 gather with 8-deep MLP -------------------------------------
__device__ __forceinline__ void gather16(const __half2* __restrict__ A2, int n, int lane,
                                         float& axo, float& ayo) {
    float ax = 0.f, ay = 0.f;
    int base = n * MAXD;
    int len = min(g_cnt[n], MAXD);
    int j = 0;
    for (; j + 8 <= len; j += 8) {
        int4 c0 = *(const int4*)&g_col[base + j];
        int4 c1 = *(const int4*)&g_col[base + j + 4];
        float2 f0 = __half22float2(__ldg(&A2[c0.x * 32 + lane]));
        float2 f1 = __half22float2(__ldg(&A2[c0.y * 32 + lane]));
        float2 f2 = __half22float2(__ldg(&A2[c0.z * 32 + lane]));
        float2 f3 = __half22float2(__ldg(&A2[c0.w * 32 + lane]));
        float2 f4 = __half22float2(__ldg(&A2[c1.x * 32 + lane]));
        float2 f5 = __half22float2(__ldg(&A2[c1.y * 32 + lane]));
        float2 f6 = __half22float2(__ldg(&A2[c1.z * 32 + lane]));
        float2 f7 = __half22float2(__ldg(&A2[c1.w * 32 + lane]));
        ax += (f0.x + f1.x) + (f2.x + f3.x) + (f4.x + f5.x) + (f6.x + f7.x);
        ay += (f0.y + f1.y) + (f2.y + f3.y) + (f4.y + f5.y) + (f6.y + f7.y);
    }
    for (; j + 4 <= len; j += 4) {
        int4 c = *(const int4*)&g_col[base + j];
        float2 f0 = __half22float2(__ldg(&A2[c.x * 32 + lane]));
        float2 f1 = __half22float2(__ldg(&A2[c.y * 32 + lane]));
        float2 f2 = __half22float2(__ldg(&A2[c.z * 32 + lane]));
        float2 f3 = __half22float2(__ldg(&A2[c.w * 32 + lane]));
        ax += (f0.x + f1.x) + (f2.x + f3.x);
        ay += (f0.y + f1.y) + (f2.y + f3.y);
    }
    for (; j < len; j++) {
        float2 f = __half22float2(__ldg(&A2[g_col[base + j] * 32 + lane]));
        ax += f.x;
        ay += f.y;
    }
    float2 sv = __half22float2(A2[n * 32 + lane]);
    axo = ax + sv.x;
    ayo = ay + sv.y;
}

// ------- layer 0: agg(xs) -> h0 = relu(y@W_in + b) -> g_h (fp16) ---------------
// lane = (e,f): e = lane>>2 handles edge j+e, f = lane&3 the feature.
// Reduction: 3-stride butterfly on ONE scalar, then 4 broadcast shuffles.
__global__ void k_aggx(const float* __restrict__ W, const float* __restrict__ bias) {
    __shared__ float2 Ws2[4 * 32];
    __shared__ float2 Bs2[32];
    if (threadIdx.x < 128) {
        int k = threadIdx.x >> 5, l = threadIdx.x & 31;
        Ws2[k * 32 + l] = make_float2(W[k * HID + 2 * l], W[k * HID + 2 * l + 1]);
    }
    if (threadIdx.x < 32)
        Bs2[threadIdx.x] = make_float2(bias[2 * threadIdx.x], bias[2 * threadIdx.x + 1]);
    __syncthreads();

    int warp = (blockIdx.x * blockDim.x + threadIdx.x) >> 5;
    int lane = threadIdx.x & 31;
    int n0 = warp * NPW;
    if (n0 >= NN) return;
    int e = lane >> 2, f = lane & 3;

    #pragma unroll
    for (int i = 0; i < NPW; i++) {
        int n = n0 + i;
        int base = n * MAXD;
        int len = min(g_cnt[n], MAXD);
        float acc = 0.f;
        for (int j = 0; j < len; j += 8) {
            int je = j + e;
            if (je < len) {
                int s = g_col[base + je];
                acc += __ldg(&g_xs[s * 4 + f]);
            }
        }
        // butterfly over e-bits (lane strides 4, 8, 16)
        acc += __shfl_xor_sync(0xffffffffu, acc, 4);
        acc += __shfl_xor_sync(0xffffffffu, acc, 8);
        acc += __shfl_xor_sync(0xffffffffu, acc, 16);
        // lanes 0..3 now hold the 4 feature sums; broadcast
        float s0 = __shfl_sync(0xffffffffu, acc, 0);
        float s1 = __shfl_sync(0xffffffffu, acc, 1);
        float s2 = __shfl_sync(0xffffffffu, acc, 2);
        float s3 = __shfl_sync(0xffffffffu, acc, 3);
        float di = g_dinv[n];
        float4 sv = ((const float4*)g_xs)[n];
        float y0 = di * (s0 + sv.x);
        float y1 = di * (s1 + sv.y);
        float y2 = di * (s2 + sv.z);
        float y3 = di * (s3 + sv.w);
        float2 b2 = Bs2[lane];
        float a0 = b2.x, a1 = b2.y;
        float2 w0 = Ws2[0 * 32 + lane], w1 = Ws2[1 * 32 + lane];
        float2 w2 = Ws2[2 * 32 + lane], w3 = Ws2[3 * 32 + lane];
        a0 = fmaf(y0, w0.x, a0); a1 = fmaf(y0, w0.y, a1);
        a0 = fmaf(y1, w1.x, a0); a1 = fmaf(y1, w1.y, a1);
        a0 = fmaf(y2, w2.x, a0); a1 = fmaf(y2, w2.y, a1);
        a0 = fmaf(y3, w3.x, a0); a1 = fmaf(y3, w3.y, a1);
        a0 = fmaxf(a0, 0.f);
        a1 = fmaxf(a1, 0.f);
        ((__half2*)g_h)[n * 32 + lane] = __floats2half2_rn(a0, a1);
    }
}

// ---- tensor-core GEMM: M = dinv .* (H @ W),  H[NNP,64] fp16, W fp32->fp16 -----
__global__ void k_wmma(const __half* __restrict__ H, __half* __restrict__ M,
                       const float* __restrict__ W) {
    __shared__ __half Ws[HID * HID];          // 8 KB
    __shared__ float  Os[8][16 * HID];        // 32 KB
    for (int i = threadIdx.x; i < HID * HID; i += blockDim.x)
        Ws[i] = __float2half(W[i]);
    __syncthreads();

    int w = threadIdx.x >> 5;
    int lane = threadIdx.x & 31;
    int row0 = blockIdx.x * 128 + w * 16;

    wmma::fragment<wmma::matrix_a, 16, 16, 16, __half, wmma::row_major> a[4];
    #pragma unroll
    for (int k = 0; k < 4; k++)
        wmma::load_matrix_sync(a[k], H + row0 * HID + k * 16, HID);

    #pragma unroll
    for (int nt = 0; nt < 4; nt++) {
        wmma::fragment<wmma::accumulator, 16, 16, 16, float> acc;
        wmma::fill_fragment(acc, 0.f);
        #pragma unroll
        for (int k = 0; k < 4; k++) {
            wmma::fragment<wmma::matrix_b, 16, 16, 16, __half, wmma::row_major> b;
            wmma::load_matrix_sync(b, Ws + (k * 16) * HID + nt * 16, HID);
            wmma::mma_sync(acc, a[k], b, acc);
        }
        wmma::store_matrix_sync(&Os[w][nt * 16], acc, HID, wmma::mem_row_major);
    }
    __syncwarp();

    for (int idx = lane; idx < 16 * 32; idx += 32) {
        int r = idx >> 5, c = idx & 31;
        float di = g_dinv[row0 + r];
        float f0 = Os[w][r * HID + 2 * c];
        float f1 = Os[w][r * HID + 2 * c + 1];
        ((__half2*)M)[(row0 + r) * 32 + c] = __floats2half2_rn(f0 * di, f1 * di);
    }
}

// ---- hidden gather: h' = relu(di*(agg m) + b) -> g_h (fp16) -------------------
__global__ void k_agg(const __half* __restrict__ srcbuf, __half* __restrict__ dstbuf,
                      const float* __restrict__ bias) {
    __shared__ float2 Bs2[32];
    if (threadIdx.x < 32)
        Bs2[threadIdx.x] = make_float2(bias[2 * threadIdx.x], bias[2 * threadIdx.x + 1]);
    __syncthreads();

    int warp = (blockIdx.x * blockDim.x + threadIdx.x) >> 5;
    int lane = threadIdx.x & 31;
    int n0 = warp * NPW;
    if (n0 >= NN) return;
    const __half2* A2 = (const __half2*)srcbuf;

    #pragma unroll
    for (int i = 0; i < NPW; i++) {
        int n = n0 + i;
        float ax, ay;
        gather16(A2, n, lane, ax, ay);
        float di = g_dinv[n];
        float2 b2 = Bs2[lane];
        ax = fmaxf(fmaf(di, ax, b2.x), 0.f);
        ay = fmaxf(fmaf(di, ay, b2.y), 0.f);
        ((__half2*)dstbuf)[n * 32 + lane] = __floats2half2_rn(ax, ay);
    }
}

// ---- last hidden layer: gather -> h=relu(di*agg+b) -> z = di*(h.Wout) ---------
__global__ void k_agg_last(const __half* __restrict__ srcbuf,
                           const float* __restrict__ bias, const float* __restrict__ Wout) {
    int warp = (blockIdx.x * blockDim.x + threadIdx.x) >> 5;
    int lane = threadIdx.x & 31;
    if (warp >= NN) return;
    int n = warp;
    const __half2* A2 = (const __half2*)srcbuf;
    float ax, ay;
    gather16(A2, n, lane, ax, ay);
    float di = g_dinv[n];
    float2 b2 = ((const float2*)bias)[lane];
    ax = fmaxf(fmaf(di, ax, b2.x), 0.f);
    ay = fmaxf(fmaf(di, ay, b2.y), 0.f);
    float2 w2 = ((const float2*)Wout)[lane];
    float s = ax * w2.x + ay * w2.y;
    #pragma unroll
    for (int o = 16; o; o >>= 1) s += __shfl_xor_sync(0xffffffffu, s, o);
    if (lane == 0) g_z[n] = di * s;
}

// ---- final scalar aggregation ------------------------------------------------
__global__ void k_agg_scalar(float* __restrict__ out, const float* __restrict__ b_out) {
    int n = blockIdx.x * blockDim.x + threadIdx.x;
    if (n < NN) {
        float acc = 0.f;
        int base = n * MAXD;
        int len = min(g_cnt[n], MAXD);
        int j = 0;
        for (; j + 8 <= len; j += 8) {
            int4 c0 = *(const int4*)&g_col[base + j];
            int4 c1 = *(const int4*)&g_col[base + j + 4];
            float z0 = __ldg(&g_z[c0.x]), z1 = __ldg(&g_z[c0.y]);
            float z2 = __ldg(&g_z[c0.z]), z3 = __ldg(&g_z[c0.w]);
            float z4 = __ldg(&g_z[c1.x]), z5 = __ldg(&g_z[c1.y]);
            float z6 = __ldg(&g_z[c1.z]), z7 = __ldg(&g_z[c1.w]);
            acc += (z0 + z1) + (z2 + z3) + (z4 + z5) + (z6 + z7);
        }
        for (; j + 4 <= len; j += 4) {
            int4 c = *(const int4*)&g_col[base + j];
            acc += __ldg(&g_z[c.x]) + __ldg(&g_z[c.y]) + __ldg(&g_z[c.z]) + __ldg(&g_z[c.w]);
        }
        for (; j < len; j++) acc += __ldg(&g_z[g_col[base + j]]);
        acc += g_z[n];
        out[n] = fmaf(g_dinv[n], acc, b_out[0]);
    }
}

// ---------------- launch ------------------------------------------------------
extern "C" void kernel_launch(void* const* d_in, const int* in_sizes, int n_in,
                              void* d_out, int out_size) {
    const float* x     = (const float*)d_in[0];
    const int*   ei    = (const int*)d_in[1];
    const float* W_in  = (const float*)d_in[2];
    const float* b_in  = (const float*)d_in[3];
    const float* W_h   = (const float*)d_in[4];
    const float* b_h   = (const float*)d_in[5];
    const float* W_out = (const float*)d_in[6];
    const float* b_out = (const float*)d_in[7];
    float*       out   = (float*)d_out;

    const int TB = 256;
    const int gN  = (NN + TB - 1) / TB;
    const int gE  = (NE + TB - 1) / TB;
    const int gW  = (NN * 32 + TB - 1) / TB;            // warp per node
    const int nWarp4 = (NN + NPW - 1) / NPW;            // 12500
    const int gW4 = (nWarp4 * 32 + TB - 1) / TB;        // gather kernels
    const int gMM = NNP / 128;                          // 391 wmma blocks

    __half* h; cudaGetSymbolAddress((void**)&h, g_h);
    __half* m; cudaGetSymbolAddress((void**)&m, g_m);
    int* cnt; cudaGetSymbolAddress((void**)&cnt, g_cnt);

    // CSR build (cnt zeroed via async memset — capturable, no SM pass)
    cudaMemsetAsync(cnt, 0, NN * sizeof(int));
    k_scatter_count<<<gE, TB>>>(ei);
    k_dinv_xs<<<gN, TB>>>(x);

    // layer 0: agg(x) -> h0 = relu(y@W_in+b) -> g_h
    k_aggx<<<gW4, TB>>>(W_in, b_in);

    // hidden layers 1-2: tensor-core GEMM then gather
    for (int l = 0; l < 2; l++) {
        k_wmma<<<gMM, TB>>>(h, m, W_h + l * HID * HID);
        k_agg<<<gW4, TB>>>(m, h, b_h + l * HID);
    }
    // layer 3: GEMM then gather fused with output GEMV
    k_wmma<<<gMM, TB>>>(h, m, W_h + 2 * HID * HID);
    k_agg_last<<<gW, TB>>>(m, b_h + 2 * HID, W_out);

    // out = di*(sum z + z_self) + b_out
    k_agg_scalar<<<gN, TB>>>(out, b_out);
}